// round 15
// baseline (speedup 1.0000x reference)
#include <cuda_runtime.h>
#include <cstdint>

// ---------------------------------------------------------------------------
// Inverse NTT over F_P, P = 2013265921 = 15*2^27 + 1, N = 2^22, C = 4.
// int32 inputs, float32 output (confirmed rel_err == 0).
//
// Champion structure (R8, 185us) consolidated:
//   phase 1: cp.async gather | R8 | R4 | R8 | R8 | staged 32B scratch store
//   phase 2: fused load+twist+R8 | R4 | R8 | fused R8+output   (3 barriers)
// ---------------------------------------------------------------------------

#define LOGN 22
#define NN   (1u << LOGN)
#define NH   (1u << (LOGN - 1))

static constexpr unsigned int P        = 2013265921u;
static constexpr unsigned int PINV_NEG = 2013265919u;                  // -P^{-1} mod 2^32
static constexpr unsigned long long Rmod = (1ull << 32) % P;
static constexpr unsigned int R2C = (unsigned int)((Rmod * Rmod) % P); // 2^64 mod P

// Scratch: phase-1 tile-row b, slot v at ((v&1023)<<11 + b)*2 + (v>>10).
static __device__ uint4 g_scratch[NN];   // 64 MB

__device__ __forceinline__ unsigned int SZ(unsigned int p) {
    return p ^ ((p >> 3) & 7u);
}
__device__ __forceinline__ unsigned int mulmont(unsigned int a, unsigned int bR) {
    unsigned long long t = (unsigned long long)a * bR;
    unsigned int m = (unsigned int)t * PINV_NEG;
    unsigned long long s = t + (unsigned long long)m * P;
    unsigned int r = (unsigned int)(s >> 32);
    return (r >= P) ? r - P : r;
}
__device__ __forceinline__ unsigned int addmod(unsigned int a, unsigned int b) {
    unsigned int r = a + b;  return min(r, r - P);
}
__device__ __forceinline__ unsigned int submod(unsigned int a, unsigned int b) {
    unsigned int r = a - b;  return min(r, r + P);
}
__device__ __forceinline__ void bflyT(uint4& lo, uint4& hi, unsigned int T) {
    unsigned int t0 = mulmont(hi.x, T), t1 = mulmont(hi.y, T);
    unsigned int t2 = mulmont(hi.z, T), t3 = mulmont(hi.w, T);
    uint4 l = lo;
    lo = make_uint4(addmod(l.x, t0), addmod(l.y, t1), addmod(l.z, t2), addmod(l.w, t3));
    hi = make_uint4(submod(l.x, t0), submod(l.y, t1), submod(l.z, t2), submod(l.w, t3));
}
__device__ __forceinline__ void bfly1(uint4& lo, uint4& hi) {
    uint4 l = lo, h = hi;
    lo = make_uint4(addmod(l.x, h.x), addmod(l.y, h.y), addmod(l.z, h.z), addmod(l.w, h.w));
    hi = make_uint4(submod(l.x, h.x), submod(l.y, h.y), submod(l.z, h.z), submod(l.w, h.w));
}
__device__ __forceinline__ void cp_async16(unsigned int smem_addr, const void* gptr) {
    asm volatile("cp.async.ca.shared.global [%0], [%1], 16;"
                 :: "r"(smem_addr), "l"(gptr) : "memory");
}

// ---------------------------------------------------------------------------
// Phase 1: gather + stages 1..11 on 2048-slot tiles in bit-reversed storage.
// ---------------------------------------------------------------------------
__global__ void __launch_bounds__(512) k_stage1(const uint4* __restrict__ in,
                                                const unsigned int* __restrict__ tw) {
    extern __shared__ uint4 smem[];                 // 2 tiles of 2048 + shtw
    unsigned int* shtw = (unsigned int*)(smem + 4096);

    const unsigned int tid = threadIdx.x;
    const unsigned int rb0 = 2u * blockIdx.x;
    const unsigned int jt  = tid >> 8, m = tid & 255u;
    const unsigned int tb  = jt << 11;

    // cp.async gather: 32B per thread-row (both tiles); overlaps with staging
    const unsigned int smem_base =
        (unsigned int)__cvta_generic_to_shared(smem);
    #pragma unroll
    for (int r = 0; r < 4; r++) {
        unsigned int p = tid + r * 512u;
        size_t row = ((size_t)p << 11) | rb0;
        cp_async16(smem_base + SZ(p) * 16u,            &in[row]);
        cp_async16(smem_base + (2048u + SZ(p)) * 16u,  &in[row + 1]);
    }
    asm volatile("cp.async.commit_group;" ::: "memory");

    shtw[tid]        = mulmont(tw[(size_t)tid << 11], R2C);
    shtw[tid + 512u] = mulmont(tw[(size_t)(tid + 512u) << 11], R2C);

    asm volatile("cp.async.wait_group 0;" ::: "memory");
    __syncthreads();

    uint4 x[8];
    // ---- R8a: stages 1,2,3 (bits 10,9,8); slots m + k*256 ---------------
    {
        #pragma unroll
        for (int k = 0; k < 8; k++) x[k] = smem[tb + SZ(m + (k << 8))];
        const unsigned int J  = shtw[512], K1 = shtw[256], K3 = shtw[768];
        bfly1(x[0], x[4]); bfly1(x[1], x[5]); bfly1(x[2], x[6]); bfly1(x[3], x[7]);
        bfly1(x[0], x[2]); bfly1(x[1], x[3]);
        bflyT(x[4], x[6], J); bflyT(x[5], x[7], J);
        bfly1(x[0], x[1]); bflyT(x[2], x[3], J);
        bflyT(x[4], x[5], K1); bflyT(x[6], x[7], K3);
        #pragma unroll
        for (int k = 0; k < 8; k++) smem[tb + SZ(m + (k << 8))] = x[k];
    }
    __syncthreads();

    // ---- R4: stages 4,5 (bits 7,6); quads {p0,+64,+128,+192} ------------
    {
        const unsigned int lo = tid & 63u, hi = tid >> 6;      // hi < 8
        const unsigned int p0 = (hi << 8) | lo;
        const unsigned int i  = (__brev(hi) >> 29) << 6;       // rev3(hi)<<6
        const unsigned int T4 = shtw[i << 1], T5a = shtw[i], T5b = shtw[i + 512u];
        #pragma unroll
        for (int t = 0; t < 2; t++) {
            const unsigned int b = t << 11;
            uint4 x0 = smem[b + SZ(p0)],        x1 = smem[b + SZ(p0 + 64u)];
            uint4 x2 = smem[b + SZ(p0 + 128u)], x3 = smem[b + SZ(p0 + 192u)];
            bflyT(x0, x2, T4); bflyT(x1, x3, T4);              // s=4 (diff 128)
            bflyT(x0, x1, T5a); bflyT(x2, x3, T5b);            // s=5 (diff 64)
            smem[b + SZ(p0)] = x0;        smem[b + SZ(p0 + 64u)]  = x1;
            smem[b + SZ(p0 + 128u)] = x2; smem[b + SZ(p0 + 192u)] = x3;
        }
    }
    __syncthreads();

    // ---- R8b: stages 6,7,8 (bits 5,4,3); slots vb + k*8 -----------------
    {
        const unsigned int lo3 = m & 7u, hi = m >> 3;          // hi < 32
        const unsigned int vb  = (hi << 6) | lo3;
        #pragma unroll
        for (int k = 0; k < 8; k++) x[k] = smem[tb + SZ(vb + (k << 3))];
        const unsigned int i   = (__brev(hi) >> 27) << 5;      // rev5(hi)<<5
        const unsigned int TA  = shtw[i];
        const unsigned int TB0 = shtw[i >> 1], TB1 = shtw[(i >> 1) + 512u];
        const unsigned int ib  = i >> 2;
        const unsigned int TC0 = shtw[ib],        TC1 = shtw[ib + 512u];
        const unsigned int TC2 = shtw[ib + 256u], TC3 = shtw[ib + 768u];
        bflyT(x[0], x[4], TA); bflyT(x[1], x[5], TA);
        bflyT(x[2], x[6], TA); bflyT(x[3], x[7], TA);
        bflyT(x[0], x[2], TB0); bflyT(x[1], x[3], TB0);
        bflyT(x[4], x[6], TB1); bflyT(x[5], x[7], TB1);
        bflyT(x[0], x[1], TC0); bflyT(x[2], x[3], TC1);
        bflyT(x[4], x[5], TC2); bflyT(x[6], x[7], TC3);
        #pragma unroll
        for (int k = 0; k < 8; k++) smem[tb + SZ(vb + (k << 3))] = x[k];
    }
    __syncthreads();

    // ---- R8c: stages 9,10,11 (bits 2,1,0); slots 8m+k -------------------
    {
        #pragma unroll
        for (int k = 0; k < 8; k++) x[k] = smem[tb + SZ(8u * m + k)];
        const unsigned int i   = (__brev(m) >> 24) << 2;       // rev8(m)<<2
        const unsigned int TA  = shtw[i];
        const unsigned int TB0 = shtw[i >> 1], TB1 = shtw[(i >> 1) + 512u];
        const unsigned int ib  = i >> 2;
        const unsigned int TC0 = shtw[ib],        TC1 = shtw[ib + 512u];
        const unsigned int TC2 = shtw[ib + 256u], TC3 = shtw[ib + 768u];
        bflyT(x[0], x[4], TA); bflyT(x[1], x[5], TA);
        bflyT(x[2], x[6], TA); bflyT(x[3], x[7], TA);
        bflyT(x[0], x[2], TB0); bflyT(x[1], x[3], TB0);
        bflyT(x[4], x[6], TB1); bflyT(x[5], x[7], TB1);
        bflyT(x[0], x[1], TC0); bflyT(x[2], x[3], TC1);
        bflyT(x[4], x[5], TC2); bflyT(x[6], x[7], TC3);
        #pragma unroll
        for (int k = 0; k < 8; k++) smem[tb + SZ(8u * m + k)] = x[k];
    }
    __syncthreads();

    // ---- staged store: paired 32B rows into scratch ---------------------
    const unsigned int b0 = __brev(rb0) >> 21;     // < 1024
    const unsigned int b1 = b0 | 1024u;
    #pragma unroll
    for (int rr = 0; rr < 2; rr++) {
        unsigned int p = tid + rr * 512u;          // < 1024
        size_t base = ((size_t)p << 11);
        g_scratch[(base + b0) * 2 + 0] = smem[SZ(p)];
        g_scratch[(base + b0) * 2 + 1] = smem[SZ(p + 1024u)];
        g_scratch[(base + b1) * 2 + 0] = smem[2048u + SZ(p)];
        g_scratch[(base + b1) * 2 + 1] = smem[2048u + SZ(p + 1024u)];
    }
}

// ---------------------------------------------------------------------------
// Phase 2: stages 12..22 as twisted natural-order 2048-NTT per column.
// Thread-half j = tid>>8 owns column C + j*1024 (L = rev11(C)+j), m = tid&255.
// Twist for slot s = 8m+k:  w^{-L*rev11(s)} * n_inv,
//   rev11(s) = rev8(m) + 256*rev3(k)  ->  Fb * W^{rev3(k)}, W = mont(w^{-256L}).
// ---------------------------------------------------------------------------
__global__ void __launch_bounds__(512) k_stage2(float4* __restrict__ out,
                                                const unsigned int* __restrict__ tw,
                                                const unsigned int* __restrict__ ni) {
    extern __shared__ uint4 smem[];
    unsigned int* shtw = (unsigned int*)(smem + 4096);

    const unsigned int tid = threadIdx.x;
    const unsigned int C   = blockIdx.x;
    const unsigned int L0  = __brev(C) >> 21;      // even
    const unsigned int j   = tid >> 8, m = tid & 255u;
    const unsigned int tb  = j << 11;
    const unsigned int L   = L0 + j;

    shtw[tid]        = mulmont(tw[(size_t)tid << 11], R2C);
    shtw[tid + 512u] = mulmont(tw[(size_t)(tid + 512u) << 11], R2C);

    const unsigned int J  = mulmont(tw[1u << 20], R2C);
    const unsigned int K1 = mulmont(tw[1u << 19], R2C);
    const unsigned int K3 = mulmont(tw[3u << 19], R2C);

    uint4 x[8];
    // ---- fused scratch load + twist + R8a: sg 1,2,3 ---------------------
    {
        #pragma unroll
        for (int k = 0; k < 8; k++)
            x[k] = g_scratch[((((size_t)C << 11) + (8u * m + k))) * 2 + j];

        const unsigned int X   = mulmont(mulmont(ni[0], R2C), R2C); // ninv * R^2
        const unsigned int r8m = __brev(m) >> 24;                   // rev8(m)
        const unsigned int Fb  = mulmont(tw[L * r8m], X);           // exp < 2^20
        const unsigned int W1  = mulmont(tw[L << 8], R2C);          // exp < 2^21
        const unsigned int W2  = mulmont(W1, W1);
        const unsigned int W3  = mulmont(W2, W1);
        const unsigned int W4  = mulmont(W2, W2);
        const unsigned int W5  = mulmont(W4, W1);
        const unsigned int W6  = mulmont(W3, W3);
        const unsigned int W7  = mulmont(W4, W3);
        unsigned int F[8];                                          // Fb * W^{rev3(k)}
        F[0] = Fb;              F[1] = mulmont(Fb, W4);
        F[2] = mulmont(Fb, W2); F[3] = mulmont(Fb, W6);
        F[4] = mulmont(Fb, W1); F[5] = mulmont(Fb, W5);
        F[6] = mulmont(Fb, W3); F[7] = mulmont(Fb, W7);
        #pragma unroll
        for (int k = 0; k < 8; k++) {
            x[k].x = mulmont(x[k].x, F[k]); x[k].y = mulmont(x[k].y, F[k]);
            x[k].z = mulmont(x[k].z, F[k]); x[k].w = mulmont(x[k].w, F[k]);
        }
        // R8a: sg1 (diff 1), sg2 (diff 2), sg3 (diff 4)
        bfly1(x[0], x[1]); bfly1(x[2], x[3]); bfly1(x[4], x[5]); bfly1(x[6], x[7]);
        bfly1(x[0], x[2]); bflyT(x[1], x[3], J);
        bfly1(x[4], x[6]); bflyT(x[5], x[7], J);
        bfly1(x[0], x[4]); bflyT(x[1], x[5], K1);
        bflyT(x[2], x[6], J); bflyT(x[3], x[7], K3);
        #pragma unroll
        for (int k = 0; k < 8; k++) smem[tb + SZ(8u * m + k)] = x[k];
    }
    __syncthreads();

    // ---- R4: sg 4,5 (strides 8,16); quads {h0,+8,+16,+24} ---------------
    {
        const unsigned int lo3 = tid & 7u, hi = tid >> 3;      // hi < 64
        const unsigned int h0  = (hi << 5) | lo3;
        const unsigned int i   = lo3 << 6;
        const unsigned int T4 = shtw[i << 1], T5a = shtw[i], T5b = shtw[i + 512u];
        #pragma unroll
        for (int t = 0; t < 2; t++) {
            const unsigned int b = t << 11;
            uint4 x0 = smem[b + SZ(h0)],        x1 = smem[b + SZ(h0 + 8u)];
            uint4 x2 = smem[b + SZ(h0 + 16u)],  x3 = smem[b + SZ(h0 + 24u)];
            bflyT(x0, x1, T4); bflyT(x2, x3, T4);              // sg=4
            bflyT(x0, x2, T5a); bflyT(x1, x3, T5b);            // sg=5
            smem[b + SZ(h0)] = x0;        smem[b + SZ(h0 + 8u)]  = x1;
            smem[b + SZ(h0 + 16u)] = x2;  smem[b + SZ(h0 + 24u)] = x3;
        }
    }
    __syncthreads();

    // ---- R8b: sg 6,7,8 (strides 32,64,128); slots vb + k*32 -------------
    {
        const unsigned int lo5 = m & 31u, hi = m >> 5;         // hi < 8
        const unsigned int vb  = (hi << 8) | lo5;
        #pragma unroll
        for (int k = 0; k < 8; k++) x[k] = smem[tb + SZ(vb + (k << 5))];
        const unsigned int i   = lo5 << 5;
        const unsigned int TA  = shtw[i];
        const unsigned int TB0 = shtw[i >> 1], TB1 = shtw[(i >> 1) + 512u];
        const unsigned int ib  = i >> 2;
        const unsigned int TC0 = shtw[ib],        TC1 = shtw[ib + 256u];
        const unsigned int TC2 = shtw[ib + 512u], TC3 = shtw[ib + 768u];
        bflyT(x[0], x[1], TA); bflyT(x[2], x[3], TA);
        bflyT(x[4], x[5], TA); bflyT(x[6], x[7], TA);
        bflyT(x[0], x[2], TB0); bflyT(x[1], x[3], TB1);
        bflyT(x[4], x[6], TB0); bflyT(x[5], x[7], TB1);
        bflyT(x[0], x[4], TC0); bflyT(x[1], x[5], TC1);
        bflyT(x[2], x[6], TC2); bflyT(x[3], x[7], TC3);
        #pragma unroll
        for (int k = 0; k < 8; k++) smem[tb + SZ(vb + (k << 5))] = x[k];
    }
    __syncthreads();

    // ---- R8c: sg 9,10,11 (strides 256,512,1024); slots k*256+m; fused out
    {
        #pragma unroll
        for (int k = 0; k < 8; k++) x[k] = smem[tb + SZ((k << 8) + m)];
        const unsigned int i   = m << 2;
        const unsigned int TA  = shtw[i];
        const unsigned int TB0 = shtw[i >> 1], TB1 = shtw[(i >> 1) + 512u];
        const unsigned int TC0 = shtw[m],        TC1 = shtw[m + 256u];
        const unsigned int TC2 = shtw[m + 512u], TC3 = shtw[m + 768u];
        bflyT(x[0], x[1], TA); bflyT(x[2], x[3], TA);
        bflyT(x[4], x[5], TA); bflyT(x[6], x[7], TA);
        bflyT(x[0], x[2], TB0); bflyT(x[1], x[3], TB1);
        bflyT(x[4], x[6], TB0); bflyT(x[5], x[7], TB1);
        bflyT(x[0], x[4], TC0); bflyT(x[1], x[5], TC1);
        bflyT(x[2], x[6], TC2); bflyT(x[3], x[7], TC3);
        #pragma unroll
        for (int k = 0; k < 8; k++) {
            size_t row = (((size_t)((k << 8) + m)) << 11) | L;
            out[row] = make_float4((float)x[k].x, (float)x[k].y,
                                   (float)x[k].z, (float)x[k].w);
        }
    }
}

// ---------------------------------------------------------------------------

extern "C" void kernel_launch(void* const* d_in, const int* in_sizes, int n_in,
                              void* d_out, int out_size) {
    const void* p_in = (n_in > 0) ? d_in[0] : nullptr;
    const void* p_tw = (n_in > 1) ? d_in[1] : nullptr;
    const void* p_ni = (n_in > 2) ? d_in[2] : nullptr;
    for (int i = 0; i < n_in; i++) {
        unsigned int sz = (unsigned int)in_sizes[i];
        if (sz == NN * 4u) p_in = d_in[i];
        else if (sz == NH) p_tw = d_in[i];
        else if (sz == 1u) p_ni = d_in[i];
    }

    const int smem = 4096 * (int)sizeof(uint4) + 1024 * (int)sizeof(unsigned int); // 69632
    cudaFuncSetAttribute(k_stage1, cudaFuncAttributeMaxDynamicSharedMemorySize, smem);
    cudaFuncSetAttribute(k_stage2, cudaFuncAttributeMaxDynamicSharedMemorySize, smem);

    k_stage1<<< 1024, 512, smem >>>((const uint4*)p_in, (const unsigned int*)p_tw);
    k_stage2<<< 1024, 512, smem >>>((float4*)d_out, (const unsigned int*)p_tw,
                                    (const unsigned int*)p_ni);
    (void)out_size;
}

// round 16
// speedup vs baseline: 1.0855x; 1.0855x over previous
#include <cuda_runtime.h>
#include <cstdint>

// ---------------------------------------------------------------------------
// Inverse NTT over F_P, P = 2013265921 = 15*2^27 + 1, N = 2^22, C = 4.
// int32 inputs, float32 output (confirmed rel_err == 0).
//
// Champion structure (R8, 185.1us), plus streaming cache hints on all global
// traffic (no L1 reuse exists for it; keeps l1tex for the LDS butterflies):
//   phase 1: staged 32B gather (__ldcs) | R8 | R4 | R8 | R8 | 32B scratch (__stcg)
//   phase 2: scratch (__ldcg) + twist | R8 | R4 | R8 | R8 | output (__stcs)
// ---------------------------------------------------------------------------

#define LOGN 22
#define NN   (1u << LOGN)
#define NH   (1u << (LOGN - 1))

static constexpr unsigned int P        = 2013265921u;
static constexpr unsigned int PINV_NEG = 2013265919u;                  // -P^{-1} mod 2^32
static constexpr unsigned long long Rmod = (1ull << 32) % P;
static constexpr unsigned int R2C = (unsigned int)((Rmod * Rmod) % P); // 2^64 mod P

// Scratch: phase-1 tile-row b, slot v at ((v&1023)<<11 + b)*2 + (v>>10).
static __device__ uint4 g_scratch[NN];   // 64 MB

__device__ __forceinline__ unsigned int SZ(unsigned int p) {
    return p ^ ((p >> 3) & 7u);
}
__device__ __forceinline__ unsigned int mulmont(unsigned int a, unsigned int bR) {
    unsigned long long t = (unsigned long long)a * bR;
    unsigned int m = (unsigned int)t * PINV_NEG;
    unsigned long long s = t + (unsigned long long)m * P;
    unsigned int r = (unsigned int)(s >> 32);
    return (r >= P) ? r - P : r;
}
__device__ __forceinline__ unsigned int addmod(unsigned int a, unsigned int b) {
    unsigned int r = a + b;  return min(r, r - P);
}
__device__ __forceinline__ unsigned int submod(unsigned int a, unsigned int b) {
    unsigned int r = a - b;  return min(r, r + P);
}
__device__ __forceinline__ void bflyT(uint4& lo, uint4& hi, unsigned int T) {
    unsigned int t0 = mulmont(hi.x, T), t1 = mulmont(hi.y, T);
    unsigned int t2 = mulmont(hi.z, T), t3 = mulmont(hi.w, T);
    uint4 l = lo;
    lo = make_uint4(addmod(l.x, t0), addmod(l.y, t1), addmod(l.z, t2), addmod(l.w, t3));
    hi = make_uint4(submod(l.x, t0), submod(l.y, t1), submod(l.z, t2), submod(l.w, t3));
}
__device__ __forceinline__ void bfly1(uint4& lo, uint4& hi) {
    uint4 l = lo, h = hi;
    lo = make_uint4(addmod(l.x, h.x), addmod(l.y, h.y), addmod(l.z, h.z), addmod(l.w, h.w));
    hi = make_uint4(submod(l.x, h.x), submod(l.y, h.y), submod(l.z, h.z), submod(l.w, h.w));
}

// ---------------------------------------------------------------------------
// Phase 1: gather + stages 1..11 on 2048-slot tiles in bit-reversed storage.
// ---------------------------------------------------------------------------
__global__ void __launch_bounds__(512) k_stage1(const uint4* __restrict__ in,
                                                const unsigned int* __restrict__ tw) {
    extern __shared__ uint4 smem[];                 // 2 tiles of 2048 + shtw
    unsigned int* shtw = (unsigned int*)(smem + 4096);

    const unsigned int tid = threadIdx.x;
    const unsigned int rb0 = 2u * blockIdx.x;
    const unsigned int jt  = tid >> 8, m = tid & 255u;
    const unsigned int tb  = jt << 11;

    shtw[tid]        = mulmont(tw[(size_t)tid << 11], R2C);
    shtw[tid + 512u] = mulmont(tw[(size_t)(tid + 512u) << 11], R2C);

    // staged gather: 32B per thread-row (both tiles), streaming (no L1 reuse)
    #pragma unroll
    for (int r = 0; r < 4; r++) {
        unsigned int p = tid + r * 512u;
        size_t row = ((size_t)p << 11) | rb0;
        smem[SZ(p)]         = __ldcs(&in[row]);
        smem[2048u + SZ(p)] = __ldcs(&in[row + 1]);
    }
    __syncthreads();

    uint4 x[8];
    // ---- R8a: stages 1,2,3 (bits 10,9,8); slots m + k*256 ---------------
    {
        #pragma unroll
        for (int k = 0; k < 8; k++) x[k] = smem[tb + SZ(m + (k << 8))];
        const unsigned int J  = shtw[512], K1 = shtw[256], K3 = shtw[768];
        bfly1(x[0], x[4]); bfly1(x[1], x[5]); bfly1(x[2], x[6]); bfly1(x[3], x[7]);
        bfly1(x[0], x[2]); bfly1(x[1], x[3]);
        bflyT(x[4], x[6], J); bflyT(x[5], x[7], J);
        bfly1(x[0], x[1]); bflyT(x[2], x[3], J);
        bflyT(x[4], x[5], K1); bflyT(x[6], x[7], K3);
        #pragma unroll
        for (int k = 0; k < 8; k++) smem[tb + SZ(m + (k << 8))] = x[k];
    }
    __syncthreads();

    // ---- R4: stages 4,5 (bits 7,6); quads {p0,+64,+128,+192} ------------
    {
        const unsigned int lo = tid & 63u, hi = tid >> 6;      // hi < 8
        const unsigned int p0 = (hi << 8) | lo;
        const unsigned int i  = (__brev(hi) >> 29) << 6;       // rev3(hi)<<6
        const unsigned int T4 = shtw[i << 1], T5a = shtw[i], T5b = shtw[i + 512u];
        #pragma unroll
        for (int t = 0; t < 2; t++) {
            const unsigned int b = t << 11;
            uint4 x0 = smem[b + SZ(p0)],        x1 = smem[b + SZ(p0 + 64u)];
            uint4 x2 = smem[b + SZ(p0 + 128u)], x3 = smem[b + SZ(p0 + 192u)];
            bflyT(x0, x2, T4); bflyT(x1, x3, T4);              // s=4 (diff 128)
            bflyT(x0, x1, T5a); bflyT(x2, x3, T5b);            // s=5 (diff 64)
            smem[b + SZ(p0)] = x0;        smem[b + SZ(p0 + 64u)]  = x1;
            smem[b + SZ(p0 + 128u)] = x2; smem[b + SZ(p0 + 192u)] = x3;
        }
    }
    __syncthreads();

    // ---- R8b: stages 6,7,8 (bits 5,4,3); slots vb + k*8 -----------------
    {
        const unsigned int lo3 = m & 7u, hi = m >> 3;          // hi < 32
        const unsigned int vb  = (hi << 6) | lo3;
        #pragma unroll
        for (int k = 0; k < 8; k++) x[k] = smem[tb + SZ(vb + (k << 3))];
        const unsigned int i   = (__brev(hi) >> 27) << 5;      // rev5(hi)<<5
        const unsigned int TA  = shtw[i];
        const unsigned int TB0 = shtw[i >> 1], TB1 = shtw[(i >> 1) + 512u];
        const unsigned int ib  = i >> 2;
        const unsigned int TC0 = shtw[ib],        TC1 = shtw[ib + 512u];
        const unsigned int TC2 = shtw[ib + 256u], TC3 = shtw[ib + 768u];
        bflyT(x[0], x[4], TA); bflyT(x[1], x[5], TA);
        bflyT(x[2], x[6], TA); bflyT(x[3], x[7], TA);
        bflyT(x[0], x[2], TB0); bflyT(x[1], x[3], TB0);
        bflyT(x[4], x[6], TB1); bflyT(x[5], x[7], TB1);
        bflyT(x[0], x[1], TC0); bflyT(x[2], x[3], TC1);
        bflyT(x[4], x[5], TC2); bflyT(x[6], x[7], TC3);
        #pragma unroll
        for (int k = 0; k < 8; k++) smem[tb + SZ(vb + (k << 3))] = x[k];
    }
    __syncthreads();

    // ---- R8c: stages 9,10,11 (bits 2,1,0); slots 8m+k -------------------
    {
        #pragma unroll
        for (int k = 0; k < 8; k++) x[k] = smem[tb + SZ(8u * m + k)];
        const unsigned int i   = (__brev(m) >> 24) << 2;       // rev8(m)<<2
        const unsigned int TA  = shtw[i];
        const unsigned int TB0 = shtw[i >> 1], TB1 = shtw[(i >> 1) + 512u];
        const unsigned int ib  = i >> 2;
        const unsigned int TC0 = shtw[ib],        TC1 = shtw[ib + 512u];
        const unsigned int TC2 = shtw[ib + 256u], TC3 = shtw[ib + 768u];
        bflyT(x[0], x[4], TA); bflyT(x[1], x[5], TA);
        bflyT(x[2], x[6], TA); bflyT(x[3], x[7], TA);
        bflyT(x[0], x[2], TB0); bflyT(x[1], x[3], TB0);
        bflyT(x[4], x[6], TB1); bflyT(x[5], x[7], TB1);
        bflyT(x[0], x[1], TC0); bflyT(x[2], x[3], TC1);
        bflyT(x[4], x[5], TC2); bflyT(x[6], x[7], TC3);
        #pragma unroll
        for (int k = 0; k < 8; k++) smem[tb + SZ(8u * m + k)] = x[k];
    }
    __syncthreads();

    // ---- staged store: paired 32B rows into scratch (L2-only) -----------
    const unsigned int b0 = __brev(rb0) >> 21;     // < 1024
    const unsigned int b1 = b0 | 1024u;
    #pragma unroll
    for (int rr = 0; rr < 2; rr++) {
        unsigned int p = tid + rr * 512u;          // < 1024
        size_t base = ((size_t)p << 11);
        __stcg(&g_scratch[(base + b0) * 2 + 0], smem[SZ(p)]);
        __stcg(&g_scratch[(base + b0) * 2 + 1], smem[SZ(p + 1024u)]);
        __stcg(&g_scratch[(base + b1) * 2 + 0], smem[2048u + SZ(p)]);
        __stcg(&g_scratch[(base + b1) * 2 + 1], smem[2048u + SZ(p + 1024u)]);
    }
}

// ---------------------------------------------------------------------------
// Phase 2: stages 12..22 as twisted natural-order 2048-NTT per column.
// Tile C: columns C (tile 0, L0 = rev11(C), even) and C+1024 (tile 1, L0+1).
// Twist w^{-L*rev11(h)} * n_inv folded into the load phase.
// ---------------------------------------------------------------------------
__global__ void __launch_bounds__(512) k_stage2(float4* __restrict__ out,
                                                const unsigned int* __restrict__ tw,
                                                const unsigned int* __restrict__ ni) {
    extern __shared__ uint4 smem[];
    unsigned int* shtw = (unsigned int*)(smem + 4096);

    const unsigned int tid = threadIdx.x;
    const unsigned int C   = blockIdx.x;
    const unsigned int L0  = __brev(C) >> 21;      // even
    const unsigned int L1  = L0 + 1u;

    shtw[tid]        = mulmont(tw[(size_t)tid << 11], R2C);
    shtw[tid + 512u] = mulmont(tw[(size_t)(tid + 512u) << 11], R2C);

    // X = ninv * R^2 mod P  (so mulmont(raw_w, X) = mont(w * ninv))
    const unsigned int X = mulmont(mulmont(ni[0], R2C), R2C);
    const unsigned int W0_1 = mulmont(tw[L0], R2C),      W1_1 = mulmont(tw[L1], R2C);
    const unsigned int W0_2 = mulmont(tw[2u * L0], R2C), W1_2 = mulmont(tw[2u * L1], R2C);
    const unsigned int W0_3 = mulmont(tw[3u * L0], R2C), W1_3 = mulmont(tw[3u * L1], R2C);

    const unsigned int r9 = __brev(tid) >> 23;     // rev9(tid)
    unsigned int Fb0, Fb1;
    {
        unsigned int e0 = 4u * L0 * r9;            // < 2^22
        unsigned int v0 = tw[e0 & (NH - 1u)];
        if (e0 & NH) v0 = P - v0;                  // w^{-2^21} = -1
        Fb0 = mulmont(v0, X);
        unsigned int e1 = 4u * L1 * r9;
        unsigned int v1 = tw[e1 & (NH - 1u)];
        if (e1 & NH) v1 = P - v1;
        Fb1 = mulmont(v1, X);
    }

    #pragma unroll
    for (int k = 0; k < 4; k++) {
        unsigned int h = tid + k * 512u;
        size_t base = (((size_t)C << 11) + h) * 2;
        uint4 z0 = __ldcg(&g_scratch[base]);
        uint4 z1 = __ldcg(&g_scratch[base + 1]);
        unsigned int f0, f1;                        // correction exp = rev2(k)
        if      (k == 0) { f0 = Fb0;                f1 = Fb1;                }
        else if (k == 1) { f0 = mulmont(Fb0, W0_2); f1 = mulmont(Fb1, W1_2); }
        else if (k == 2) { f0 = mulmont(Fb0, W0_1); f1 = mulmont(Fb1, W1_1); }
        else             { f0 = mulmont(Fb0, W0_3); f1 = mulmont(Fb1, W1_3); }
        smem[SZ(h)] = make_uint4(mulmont(z0.x, f0), mulmont(z0.y, f0),
                                 mulmont(z0.z, f0), mulmont(z0.w, f0));
        smem[2048u + SZ(h)] = make_uint4(mulmont(z1.x, f1), mulmont(z1.y, f1),
                                         mulmont(z1.z, f1), mulmont(z1.w, f1));
    }
    __syncthreads();

    const unsigned int jt = tid >> 8, m = tid & 255u;
    const unsigned int tb = jt << 11;
    uint4 x[8];

    // ---- R8a: sg 1,2,3 (strides 1,2,4); slots 8m + k --------------------
    {
        #pragma unroll
        for (int k = 0; k < 8; k++) x[k] = smem[tb + SZ(8u * m + k)];
        const unsigned int J = shtw[512], K1 = shtw[256], K3 = shtw[768];
        bfly1(x[0], x[1]); bfly1(x[2], x[3]); bfly1(x[4], x[5]); bfly1(x[6], x[7]);
        bfly1(x[0], x[2]); bflyT(x[1], x[3], J);
        bfly1(x[4], x[6]); bflyT(x[5], x[7], J);
        bfly1(x[0], x[4]); bflyT(x[1], x[5], K1);
        bflyT(x[2], x[6], J); bflyT(x[3], x[7], K3);
        #pragma unroll
        for (int k = 0; k < 8; k++) smem[tb + SZ(8u * m + k)] = x[k];
    }
    __syncthreads();

    // ---- R4: sg 4,5 (strides 8,16); quads {h0,+8,+16,+24} ---------------
    {
        const unsigned int lo3 = tid & 7u, hi = tid >> 3;      // hi < 64
        const unsigned int h0  = (hi << 5) | lo3;
        const unsigned int i   = lo3 << 6;
        const unsigned int T4 = shtw[i << 1], T5a = shtw[i], T5b = shtw[i + 512u];
        #pragma unroll
        for (int t = 0; t < 2; t++) {
            const unsigned int b = t << 11;
            uint4 x0 = smem[b + SZ(h0)],        x1 = smem[b + SZ(h0 + 8u)];
            uint4 x2 = smem[b + SZ(h0 + 16u)],  x3 = smem[b + SZ(h0 + 24u)];
            bflyT(x0, x1, T4); bflyT(x2, x3, T4);              // sg=4
            bflyT(x0, x2, T5a); bflyT(x1, x3, T5b);            // sg=5
            smem[b + SZ(h0)] = x0;        smem[b + SZ(h0 + 8u)]  = x1;
            smem[b + SZ(h0 + 16u)] = x2;  smem[b + SZ(h0 + 24u)] = x3;
        }
    }
    __syncthreads();

    // ---- R8b: sg 6,7,8 (strides 32,64,128); slots vb + k*32 -------------
    {
        const unsigned int lo5 = m & 31u, hi = m >> 5;         // hi < 8
        const unsigned int vb  = (hi << 8) | lo5;
        #pragma unroll
        for (int k = 0; k < 8; k++) x[k] = smem[tb + SZ(vb + (k << 5))];
        const unsigned int i   = lo5 << 5;
        const unsigned int TA  = shtw[i];
        const unsigned int TB0 = shtw[i >> 1], TB1 = shtw[(i >> 1) + 512u];
        const unsigned int ib  = i >> 2;
        const unsigned int TC0 = shtw[ib],        TC1 = shtw[ib + 256u];
        const unsigned int TC2 = shtw[ib + 512u], TC3 = shtw[ib + 768u];
        bflyT(x[0], x[1], TA); bflyT(x[2], x[3], TA);
        bflyT(x[4], x[5], TA); bflyT(x[6], x[7], TA);
        bflyT(x[0], x[2], TB0); bflyT(x[1], x[3], TB1);
        bflyT(x[4], x[6], TB0); bflyT(x[5], x[7], TB1);
        bflyT(x[0], x[4], TC0); bflyT(x[1], x[5], TC1);
        bflyT(x[2], x[6], TC2); bflyT(x[3], x[7], TC3);
        #pragma unroll
        for (int k = 0; k < 8; k++) smem[tb + SZ(vb + (k << 5))] = x[k];
    }
    __syncthreads();

    // ---- R8c: sg 9,10,11 (strides 256,512,1024); slots k*256+m ----------
    {
        #pragma unroll
        for (int k = 0; k < 8; k++) x[k] = smem[tb + SZ((k << 8) + m)];
        const unsigned int i   = m << 2;
        const unsigned int TA  = shtw[i];
        const unsigned int TB0 = shtw[i >> 1], TB1 = shtw[(i >> 1) + 512u];
        const unsigned int TC0 = shtw[m],        TC1 = shtw[m + 256u];
        const unsigned int TC2 = shtw[m + 512u], TC3 = shtw[m + 768u];
        bflyT(x[0], x[1], TA); bflyT(x[2], x[3], TA);
        bflyT(x[4], x[5], TA); bflyT(x[6], x[7], TA);
        bflyT(x[0], x[2], TB0); bflyT(x[1], x[3], TB1);
        bflyT(x[4], x[6], TB0); bflyT(x[5], x[7], TB1);
        bflyT(x[0], x[4], TC0); bflyT(x[1], x[5], TC1);
        bflyT(x[2], x[6], TC2); bflyT(x[3], x[7], TC3);
        #pragma unroll
        for (int k = 0; k < 8; k++) smem[tb + SZ((k << 8) + m)] = x[k];
    }
    __syncthreads();

    // ---- store: adjacent column pair -> 32B float4 x2 (streaming) -------
    #pragma unroll
    for (int k = 0; k < 4; k++) {
        unsigned int h = tid + k * 512u;
        uint4 v0 = smem[SZ(h)];
        uint4 v1 = smem[2048u + SZ(h)];
        size_t row = ((size_t)h << 11) | L0;
        __stcs(&out[row],
               make_float4((float)v0.x, (float)v0.y, (float)v0.z, (float)v0.w));
        __stcs(&out[row + 1],
               make_float4((float)v1.x, (float)v1.y, (float)v1.z, (float)v1.w));
    }
}

// ---------------------------------------------------------------------------

extern "C" void kernel_launch(void* const* d_in, const int* in_sizes, int n_in,
                              void* d_out, int out_size) {
    const void* p_in = (n_in > 0) ? d_in[0] : nullptr;
    const void* p_tw = (n_in > 1) ? d_in[1] : nullptr;
    const void* p_ni = (n_in > 2) ? d_in[2] : nullptr;
    for (int i = 0; i < n_in; i++) {
        unsigned int sz = (unsigned int)in_sizes[i];
        if (sz == NN * 4u) p_in = d_in[i];
        else if (sz == NH) p_tw = d_in[i];
        else if (sz == 1u) p_ni = d_in[i];
    }

    const int smem = 4096 * (int)sizeof(uint4) + 1024 * (int)sizeof(unsigned int); // 69632
    cudaFuncSetAttribute(k_stage1, cudaFuncAttributeMaxDynamicSharedMemorySize, smem);
    cudaFuncSetAttribute(k_stage2, cudaFuncAttributeMaxDynamicSharedMemorySize, smem);

    k_stage1<<< 1024, 512, smem >>>((const uint4*)p_in, (const unsigned int*)p_tw);
    k_stage2<<< 1024, 512, smem >>>((float4*)d_out, (const unsigned int*)p_tw,
                                    (const unsigned int*)p_ni);
    (void)out_size;
}